// round 12
// baseline (speedup 1.0000x reference)
#include <cuda_runtime.h>
#include <cuda_bf16.h>
#include <cstdint>

#define NB   32
#define NOPE 2048
#define NMAC 1024
#define DIN  64
#define DOUT 128

#define OSPLIT 2
#define ORANGE (NOPE / OSPLIT)   // 1024
#define CHUNK  32
#define NCH    (ORANGE / CHUNK)  // 32

// ---------------- scratch (device globals; no allocations) ----------------
__device__ __nv_bfloat16 g_h[(size_t)NB * NOPE * DOUT];   // h_ope bf16 [b][o][k]
__device__ float g_ao [NB * NOPE];
__device__ float g_eo1[NB * NOPE];
__device__ float g_eo2[NB * NOPE];
__device__ float g_am [NB * NMAC];
__device__ float g_em1[NB * NMAC];
__device__ float g_em2[NB * NMAC];
__device__ float g_vope[DIN];
__device__ float g_vmac[DIN];
__device__ float g_numer[(size_t)OSPLIT * NB * NMAC * DOUT];  // partial numerators
__device__ float g_Z[OSPLIT][NB * NMAC];                      // partial denominators
__device__ uint32_t g_adjp[(size_t)NB * (NOPE / 32) * NMAC];  // packed adjacency bits

// ---------------- Kp: bit-pack adjacency (streaming, full-BW) ----------------
// one thread per packed word: g_adjp[b][ow][m], bit i = adj[bidx[b]][ow*32+i][m]
__global__ void __launch_bounds__(256) k_pack(const int* __restrict__ adj,
                                              const int* __restrict__ bidx)
{
    const int idx = blockIdx.x * 256 + threadIdx.x;   // [b][ow][m]
    const int m  = idx & (NMAC - 1);
    const int ow = (idx >> 10) & 63;
    const int b  = idx >> 16;
    const int aidx = bidx[b];
    const int* p = adj + ((size_t)aidx * NOPE + ow * 32) * NMAC + m;
    uint32_t w = 0;
#pragma unroll
    for (int i = 0; i < 32; ++i)
        w |= ((uint32_t)p[(size_t)i * NMAC] & 1u) << i;
    g_adjp[idx] = w;
}

// ---------------- K0: collapsed attention vectors ----------------
__global__ void k0_vec(const float* __restrict__ ow, const float* __restrict__ oa,
                       const float* __restrict__ mw, const float* __restrict__ ma)
{
    int t = threadIdx.x;
    if (t < DIN) {
        float s = 0.f;
        for (int k = 0; k < DOUT; ++k) s += ow[k * DIN + t] * oa[k];
        g_vope[t] = s;
    } else if (t < 2 * DIN) {
        int d = t - DIN;
        float s = 0.f;
        for (int k = 0; k < DOUT; ++k) s += mw[k * DIN + d] * ma[k];
        g_vmac[d] = s;
    }
}

// ---------------- K1: h_ope (bf16) + attn_ope exps ----------------
__global__ void __launch_bounds__(256) k1_ope(const float* __restrict__ feat,
                                              const float* __restrict__ wmat)
{
    __shared__ float wT_s[DIN * 129];
    __shared__ float f_s[32 * 65];
    __shared__ float v_s[DIN];
    const int t   = threadIdx.x;
    const int blk = blockIdx.x;
    const int b   = blk >> 6;
    const int o0  = (blk & 63) * 32;

    for (int i = t; i < DOUT * DIN; i += 256) {
        int k = i >> 6, d = i & 63;
        wT_s[d * 129 + k] = wmat[i];
    }
    const float* fsrc = feat + (size_t)(b * NOPE + o0) * DIN;
    for (int i = t; i < 32 * DIN; i += 256) {
        int r = i >> 6, d = i & 63;
        f_s[r * 65 + d] = fsrc[i];
    }
    if (t < DIN) v_s[t] = g_vope[t];
    __syncthreads();

    const int kg = t & 31;
    const int rg = t >> 5;
    float acc[4][4];
#pragma unroll
    for (int r = 0; r < 4; ++r)
#pragma unroll
        for (int j = 0; j < 4; ++j) acc[r][j] = 0.f;

    for (int d = 0; d < DIN; ++d) {
        float wv[4];
#pragma unroll
        for (int j = 0; j < 4; ++j) wv[j] = wT_s[d * 129 + kg + 32 * j];
#pragma unroll
        for (int r = 0; r < 4; ++r) {
            float f = f_s[(rg * 4 + r) * 65 + d];
#pragma unroll
            for (int j = 0; j < 4; ++j) acc[r][j] += f * wv[j];
        }
    }
    __nv_bfloat16* hdst = g_h + (size_t)(b * NOPE + o0) * DOUT;
#pragma unroll
    for (int r = 0; r < 4; ++r)
#pragma unroll
        for (int j = 0; j < 4; ++j)
            hdst[(rg * 4 + r) * DOUT + kg + 32 * j] = __float2bfloat16(acc[r][j]);

    if (t < 32) {
        float ao = 0.f;
        for (int d = 0; d < DIN; ++d) ao += f_s[t * 65 + d] * v_s[d];
        int idx = b * NOPE + o0 + t;
        g_ao[idx]  = ao;
        g_eo1[idx] = expf(ao);
        g_eo2[idx] = expf(0.2f * ao);
    }
}

// ---------------- K2: h_res (fp32 exact) -> d_out, + attn_mac exps ----------------
__global__ void __launch_bounds__(256) k2_mac(const float* __restrict__ feat,
                                              const float* __restrict__ wmat,
                                              float* __restrict__ out)
{
    __shared__ float wT_s[DIN * 129];
    __shared__ float f_s[32 * 65];
    __shared__ float v_s[DIN];
    const int t   = threadIdx.x;
    const int blk = blockIdx.x;
    const int b   = blk >> 5;
    const int m0  = (blk & 31) * 32;

    for (int i = t; i < DOUT * DIN; i += 256) {
        int k = i >> 6, d = i & 63;
        wT_s[d * 129 + k] = wmat[i];
    }
    const float* fsrc = feat + (size_t)(b * NMAC + m0) * DIN;
    for (int i = t; i < 32 * DIN; i += 256) {
        int r = i >> 6, d = i & 63;
        f_s[r * 65 + d] = fsrc[i];
    }
    if (t < DIN) v_s[t] = g_vmac[t];
    __syncthreads();

    const int kg = t & 31;
    const int rg = t >> 5;
    float acc[4][4];
#pragma unroll
    for (int r = 0; r < 4; ++r)
#pragma unroll
        for (int j = 0; j < 4; ++j) acc[r][j] = 0.f;

    for (int d = 0; d < DIN; ++d) {
        float wv[4];
#pragma unroll
        for (int j = 0; j < 4; ++j) wv[j] = wT_s[d * 129 + kg + 32 * j];
#pragma unroll
        for (int r = 0; r < 4; ++r) {
            float f = f_s[(rg * 4 + r) * 65 + d];
#pragma unroll
            for (int j = 0; j < 4; ++j) acc[r][j] += f * wv[j];
        }
    }
    float* odst = out + (size_t)(b * NMAC + m0) * DOUT;
#pragma unroll
    for (int r = 0; r < 4; ++r)
#pragma unroll
        for (int j = 0; j < 4; ++j)
            odst[(rg * 4 + r) * DOUT + kg + 32 * j] = acc[r][j];

    if (t < 32) {
        float am = 0.f;
        for (int d = 0; d < DIN; ++d) am += f_s[t * 65 + d] * v_s[d];
        int idx = b * NMAC + m0 + t;
        g_am[idx]  = am;
        g_em1[idx] = expf(am);
        g_em2[idx] = expf(0.2f * am);
    }
}

// ---------------- K3: fused masked-softmax aggregation ----------------
__device__ __forceinline__ void ldsm4t(uint32_t& r0, uint32_t& r1, uint32_t& r2,
                                       uint32_t& r3, uint32_t addr)
{
    asm volatile("ldmatrix.sync.aligned.m8n8.x4.trans.shared.b16 {%0,%1,%2,%3}, [%4];\n"
                 : "=r"(r0), "=r"(r1), "=r"(r2), "=r"(r3) : "r"(addr));
}
__device__ __forceinline__ void mma16816(float* c, const uint32_t* a,
                                         uint32_t b0, uint32_t b1)
{
    asm volatile("mma.sync.aligned.m16n8k16.row.col.f32.bf16.bf16.f32 "
                 "{%0,%1,%2,%3}, {%4,%5,%6,%7}, {%8,%9}, {%0,%1,%2,%3};\n"
                 : "+f"(c[0]), "+f"(c[1]), "+f"(c[2]), "+f"(c[3])
                 : "r"(a[0]), "r"(a[1]), "r"(a[2]), "r"(a[3]), "r"(b0), "r"(b1));
}
__device__ __forceinline__ void cpa16(uint32_t s, const void* g)
{
    asm volatile("cp.async.cg.shared.global [%0], [%1], 16;\n" :: "r"(s), "l"(g));
}
__device__ __forceinline__ void cpa_commit()
{
    asm volatile("cp.async.commit_group;\n" ::);
}

// dynamic smem layout (bytes); 3-stage H pipeline, packed adj in registers
#define H_PITCH   136
#define H_BYTES   (CHUNK * H_PITCH * 2)     // 8704
#define OFF_H     0
#define OFF_W     (3 * H_BYTES)                   // 26112
#define OFF_AO    (OFF_W + H_BYTES)               // 34816
#define OFF_EO1   (OFF_AO + ORANGE * 4)           // 38912
#define OFF_EO2   (OFF_EO1 + ORANGE * 4)          // 43008
#define OFF_ZS    (OFF_EO2 + ORANGE * 4)          // 47104
#define SMEM_K3   (OFF_ZS + 512)                  // 47616  (< 48KB default)

// grid 512 = 32 b x 8 m-tiles x 2 o-splits; 256 threads; 2 CTAs/SM.
__global__ void __launch_bounds__(256, 2) k3_attn(const int* __restrict__ bidx)
{
    extern __shared__ __align__(16) char sm[];
    __nv_bfloat16* Ws   = (__nv_bfloat16*)(sm + OFF_W);
    float*         aoS  = (float*)(sm + OFF_AO);
    float*         eo1S = (float*)(sm + OFF_EO1);
    float*         eo2S = (float*)(sm + OFF_EO2);
    float*         zs   = (float*)(sm + OFF_ZS);

    const int t  = threadIdx.x;
    const int bx = blockIdx.x;
    const int b  = bx >> 4;
    const int mt = (bx >> 1) & 7;
    const int os = bx & 1;
    const int m0 = mt * 128;
    const int o0 = os * ORANGE;

    const uint32_t smbase = (uint32_t)__cvta_generic_to_shared(sm);
    const char* hgbase = (const char*)(g_h + ((size_t)b * NOPE + o0) * DOUT);

    const int m  = t & 127;
    const int oh = t >> 7;

    // packed adjacency: one word per chunk per thread (layout [b][ow][m])
    const uint32_t* adjw = g_adjp + ((size_t)b * (NOPE / 32) + (o0 >> 5)) * NMAC + m0 + m;

    // stage H chunk ch into buffer buf
    auto stageH = [&](int ch, int buf) {
        const char* hg = hgbase + (size_t)ch * CHUNK * DOUT * 2;
        uint32_t hD = smbase + OFF_H + (uint32_t)(buf * H_BYTES);
#pragma unroll
        for (int j = 0; j < 2; ++j) {
            int i = t + 256 * j, r = i >> 4, s = i & 15;
            cpa16(hD + (uint32_t)(r * H_PITCH * 2 + s * 16),
                  hg + (size_t)r * DOUT * 2 + s * 16);
        }
    };

    // prologue: H chunks 0,1 in flight; adj word 0 in register
    stageH(0, 0); cpa_commit();
    stageH(1, 1); cpa_commit();
    uint32_t wcur = __ldg(adjw);

    // per-o scalars for this CTA's o-range (overlaps prologue loads)
    {
        const float* a0 = g_ao  + b * NOPE + o0;
        const float* e1 = g_eo1 + b * NOPE + o0;
        const float* e2 = g_eo2 + b * NOPE + o0;
        for (int i = t; i < ORANGE; i += 256) {
            aoS[i]  = a0[i];
            eo1S[i] = e1[i];
            eo2S[i] = e2[i];
        }
    }

    const float amv = g_am [b * NMAC + m0 + m];
    const float em1 = g_em1[b * NMAC + m0 + m];
    const float em2 = g_em2[b * NMAC + m0 + m];
    const float negam = -amv;

    const int warp = t >> 5, lane = t & 31;
    const int kw   = warp * 16;
    const int g    = lane >> 2, tig = lane & 3;

    const int a_or = (lane & 7) + ((lane & 16) >> 1);
    const uint32_t aAdr0 = smbase + OFF_H + (uint32_t)((a_or * H_PITCH + kw + (lane & 8)) * 2);
    const uint32_t aBdr  = smbase + OFF_W + (uint32_t)(lane * H_PITCH * 2);

    float acc[64];
#pragma unroll
    for (int i = 0; i < 64; ++i) acc[i] = 0.f;
    float zacc = 0.f;

    for (int ch = 0; ch < NCH; ++ch) {
        const int buf = ch % 3;
        asm volatile("cp.async.wait_group 1;\n" ::);   // H chunk ch landed
        __syncthreads();                                // visible; old buffer free

        if (ch + 2 < NCH) stageH(ch + 2, (ch + 2) % 3);
        cpa_commit();

        // prefetch next adjacency word (latency covered by W-gen + mma)
        uint32_t wnext = 0;
        if (ch + 1 < NCH) wnext = __ldg(adjw + (size_t)(ch + 1) * NMAC);

        // ---- W-gen from packed bits ----
        {
            const int ob = ch * CHUNK;
            const uint32_t bits = wcur;
#pragma unroll
            for (int j = 0; j < 16; ++j) {
                int ol = oh + 2 * j;
                float w = 0.f;
                if ((bits >> ol) & 1u) {
                    float ao = aoS[ob + ol];
                    w = (ao >= negam) ? eo1S[ob + ol] * em1 : eo2S[ob + ol] * em2;
                }
                Ws[ol * H_PITCH + m] = __float2bfloat16(w);
                zacc += w;
            }
        }
        __syncthreads();

        // ---- mma phase (32 o per chunk) ----
        const uint32_t aAdr = aAdr0 + (uint32_t)(buf * H_BYTES);
        uint32_t A0[4], A1[4];
        ldsm4t(A0[0], A0[1], A0[2], A0[3], aAdr);
        ldsm4t(A1[0], A1[1], A1[2], A1[3], aAdr + 16 * H_PITCH * 2);
#pragma unroll
        for (int nt = 0; nt < 16; ++nt) {
            uint32_t B0, B1, B2, B3;
            ldsm4t(B0, B1, B2, B3, aBdr + (uint32_t)(nt * 16));
            mma16816(acc + nt * 4, A0, B0, B1);
            mma16816(acc + nt * 4, A1, B2, B3);
        }
        wcur = wnext;
    }

    // ---- partial Z reduction + store ----
    __syncthreads();
    if (t < 128) zs[t] = zacc;
    __syncthreads();
    if (t >= 128) zs[t - 128] += zacc;
    __syncthreads();
    if (t < 128) g_Z[os][b * NMAC + m0 + t] = zs[t];

    // ---- store partial numerator ----
    float* nb = g_numer + (((size_t)os * NB + b) * NMAC + m0) * DOUT;
#pragma unroll
    for (int nt = 0; nt < 16; ++nt) {
        int ma = nt * 8 + tig * 2;
        int k  = kw + g;
        float* p0 = nb + (size_t)ma * DOUT + k;
        float* p1 = nb + (size_t)(ma + 1) * DOUT + k;
        p0[0] = acc[nt * 4 + 0];
        p1[0] = acc[nt * 4 + 1];
        p0[8] = acc[nt * 4 + 2];
        p1[8] = acc[nt * 4 + 3];
    }
}

// ---------------- K4: combine partials, normalize, add to residual ----------------
__global__ void __launch_bounds__(256) k4_norm(float* __restrict__ out)
{
    const size_t idx = (size_t)blockIdx.x * 256 + threadIdx.x;
    const int bm = (int)(idx >> 7);
    const float z = g_Z[0][bm] + g_Z[1][bm];
    const float n = g_numer[idx] + g_numer[(size_t)NB * NMAC * DOUT + idx];
    out[idx] += n / z;
}

// ---------------- launch ----------------
extern "C" void kernel_launch(void* const* d_in, const int* in_sizes, int n_in,
                              void* d_out, int out_size)
{
    const int*   adj  = (const int*)d_in[0];
    const int*   bidx = (const int*)d_in[1];
    const float* fop  = (const float*)d_in[2];
    const float* fma  = (const float*)d_in[3];
    const float* ow   = (const float*)d_in[4];
    const float* mw   = (const float*)d_in[5];
    const float* oa   = (const float*)d_in[6];
    const float* ma   = (const float*)d_in[7];
    const float* rw   = (const float*)d_in[8];
    float* out = (float*)d_out;

    k_pack<<<(NB * (NOPE / 32) * NMAC) / 256, 256>>>(adj, bidx);
    k0_vec<<<1, 128>>>(ow, oa, mw, ma);
    k1_ope<<<NB * (NOPE / 32), 256>>>(fop, ow);
    k2_mac<<<NB * (NMAC / 32), 256>>>(fma, rw, out);
    k3_attn<<<NB * 8 * OSPLIT, 256, SMEM_K3>>>(bidx);
    k4_norm<<<(NB * NMAC * DOUT) / 256, 256>>>(out);
}

// round 14
// speedup vs baseline: 1.0859x; 1.0859x over previous
#include <cuda_runtime.h>
#include <cuda_bf16.h>
#include <cstdint>

#define NB   32
#define NOPE 2048
#define NMAC 1024
#define DIN  64
#define DOUT 128

#define CHUNK  32
#define NCH    (NOPE / CHUNK)    // 64

#define PACK_BLOCKS ((NB * (NOPE / 32) * NMAC) / 256)   // 8192
#define K1_BLOCKS   (NB * (NOPE / 32))                  // 2048
#define K2_BLOCKS   (NB * (NMAC / 32))                  // 1024

// ---------------- scratch (device globals; no allocations) ----------------
__device__ __nv_bfloat16 g_h[(size_t)NB * NOPE * DOUT];   // h_ope bf16 [b][o][k]
__device__ float g_ao [NB * NOPE];
__device__ float g_eo1[NB * NOPE];
__device__ float g_eo2[NB * NOPE];
__device__ float g_am [NB * NMAC];
__device__ float g_em1[NB * NMAC];
__device__ float g_em2[NB * NMAC];
__device__ uint32_t g_adjp[(size_t)NB * (NOPE / 32) * NMAC];  // packed adjacency bits

// ---------------- K_pre: merged pack + h_ope + h_res (grid-partitioned) ------
// blocks [0, 8192):        bit-pack adjacency (DRAM streaming)
// blocks [8192, 10240):    h_ope bf16 + attn_ope exps
// blocks [10240, 11264):   h_res fp32 -> out, + attn_mac exps
__global__ void __launch_bounds__(256) k_pre(
    const int* __restrict__ adj, const int* __restrict__ bidx,
    const float* __restrict__ fop, const float* __restrict__ owm,
    const float* __restrict__ oal,
    const float* __restrict__ fma, const float* __restrict__ rwm,
    const float* __restrict__ mwm, const float* __restrict__ mal,
    float* __restrict__ out)
{
    __shared__ float wT_s[DIN * 129];
    __shared__ float f_s[32 * 65];
    __shared__ float v_s[DIN];

    const int t   = threadIdx.x;
    const int bid = blockIdx.x;

    // ---------- branch A: adjacency bit-pack ----------
    if (bid < PACK_BLOCKS) {
        const int idx = bid * 256 + t;              // [b][ow][m]
        const int m  = idx & (NMAC - 1);
        const int ow = (idx >> 10) & 63;
        const int b  = idx >> 16;
        const int aidx = bidx[b];
        const int* p = adj + ((size_t)aidx * NOPE + ow * 32) * NMAC + m;
        uint32_t w = 0;
#pragma unroll
        for (int i = 0; i < 32; ++i)
            w |= ((uint32_t)p[(size_t)i * NMAC] & 1u) << i;
        g_adjp[idx] = w;
        return;
    }

    const bool isOpe = bid < PACK_BLOCKS + K1_BLOCKS;
    const int  blk   = isOpe ? (bid - PACK_BLOCKS) : (bid - PACK_BLOCKS - K1_BLOCKS);
    const float* feat = isOpe ? fop : fma;
    const float* wmat = isOpe ? owm : rwm;   // GEMM weights (ope_w / res_w)
    const float* avw  = isOpe ? owm : mwm;   // attention-vector weights
    const float* aal  = isOpe ? oal : mal;   // attention alphas
    const int nrowT = isOpe ? NOPE : NMAC;
    const int b  = isOpe ? (blk >> 6) : (blk >> 5);
    const int r0 = isOpe ? ((blk & 63) * 32) : ((blk & 31) * 32);

    // stage GEMM weight (transposed) + features
    for (int i = t; i < DOUT * DIN; i += 256) {
        int k = i >> 6, d = i & 63;
        wT_s[d * 129 + k] = wmat[i];
    }
    const float* fsrc = feat + (size_t)(b * nrowT + r0) * DIN;
    for (int i = t; i < 32 * DIN; i += 256) {
        int r = i >> 6, d = i & 63;
        f_s[r * 65 + d] = fsrc[i];
    }
    // local collapsed attention vector: v[d] = sum_k avw[k][d] * aal[k]
    if (t < DIN) {
        float s = 0.f;
        for (int k = 0; k < DOUT; ++k) s += avw[k * DIN + t] * aal[k];
        v_s[t] = s;
    }
    __syncthreads();

    const int kg = t & 31;
    const int rg = t >> 5;
    float acc[4][4];
#pragma unroll
    for (int r = 0; r < 4; ++r)
#pragma unroll
        for (int j = 0; j < 4; ++j) acc[r][j] = 0.f;

    for (int d = 0; d < DIN; ++d) {
        float wv[4];
#pragma unroll
        for (int j = 0; j < 4; ++j) wv[j] = wT_s[d * 129 + kg + 32 * j];
#pragma unroll
        for (int r = 0; r < 4; ++r) {
            float f = f_s[(rg * 4 + r) * 65 + d];
#pragma unroll
            for (int j = 0; j < 4; ++j) acc[r][j] += f * wv[j];
        }
    }

    if (isOpe) {
        __nv_bfloat16* hdst = g_h + (size_t)(b * NOPE + r0) * DOUT;
#pragma unroll
        for (int r = 0; r < 4; ++r)
#pragma unroll
            for (int j = 0; j < 4; ++j)
                hdst[(rg * 4 + r) * DOUT + kg + 32 * j] = __float2bfloat16(acc[r][j]);
        if (t < 32) {
            float ao = 0.f;
            for (int d = 0; d < DIN; ++d) ao += f_s[t * 65 + d] * v_s[d];
            int idx = b * NOPE + r0 + t;
            g_ao[idx]  = ao;
            g_eo1[idx] = expf(ao);
            g_eo2[idx] = expf(0.2f * ao);
        }
    } else {
        float* odst = out + (size_t)(b * NMAC + r0) * DOUT;
#pragma unroll
        for (int r = 0; r < 4; ++r)
#pragma unroll
            for (int j = 0; j < 4; ++j)
                odst[(rg * 4 + r) * DOUT + kg + 32 * j] = acc[r][j];
        if (t < 32) {
            float am = 0.f;
            for (int d = 0; d < DIN; ++d) am += f_s[t * 65 + d] * v_s[d];
            int idx = b * NMAC + r0 + t;
            g_am[idx]  = am;
            g_em1[idx] = expf(am);
            g_em2[idx] = expf(0.2f * am);
        }
    }
}

// ---------------- K3: fused masked-softmax aggregation + normalize ----------------
__device__ __forceinline__ void ldsm4t(uint32_t& r0, uint32_t& r1, uint32_t& r2,
                                       uint32_t& r3, uint32_t addr)
{
    asm volatile("ldmatrix.sync.aligned.m8n8.x4.trans.shared.b16 {%0,%1,%2,%3}, [%4];\n"
                 : "=r"(r0), "=r"(r1), "=r"(r2), "=r"(r3) : "r"(addr));
}
__device__ __forceinline__ void mma16816(float* c, const uint32_t* a,
                                         uint32_t b0, uint32_t b1)
{
    asm volatile("mma.sync.aligned.m16n8k16.row.col.f32.bf16.bf16.f32 "
                 "{%0,%1,%2,%3}, {%4,%5,%6,%7}, {%8,%9}, {%0,%1,%2,%3};\n"
                 : "+f"(c[0]), "+f"(c[1]), "+f"(c[2]), "+f"(c[3])
                 : "r"(a[0]), "r"(a[1]), "r"(a[2]), "r"(a[3]), "r"(b0), "r"(b1));
}
__device__ __forceinline__ void cpa16(uint32_t s, const void* g)
{
    asm volatile("cp.async.cg.shared.global [%0], [%1], 16;\n" :: "r"(s), "l"(g));
}
__device__ __forceinline__ void cpa_commit()
{
    asm volatile("cp.async.commit_group;\n" ::);
}

// dynamic smem layout (bytes); 3-stage H pipeline, packed adj in registers
#define H_PITCH   136
#define H_BYTES   (CHUNK * H_PITCH * 2)     // 8704
#define OFF_H     0
#define OFF_W     (3 * H_BYTES)                   // 26112
#define OFF_AO    (OFF_W + H_BYTES)               // 34816
#define OFF_EO1   (OFF_AO + NOPE * 4)             // 43008
#define OFF_EO2   (OFF_EO1 + NOPE * 4)            // 51200
#define OFF_ZS    (OFF_EO2 + NOPE * 4)            // 59392
#define SMEM_K3   (OFF_ZS + 512)                  // 59904

// grid 256 = 32 b x 8 m-tiles; 256 threads; 2 CTAs/SM -> single wave.
__global__ void __launch_bounds__(256, 2) k3_attn(float* __restrict__ out)
{
    extern __shared__ __align__(16) char sm[];
    __nv_bfloat16* Ws   = (__nv_bfloat16*)(sm + OFF_W);
    float*         aoS  = (float*)(sm + OFF_AO);
    float*         eo1S = (float*)(sm + OFF_EO1);
    float*         eo2S = (float*)(sm + OFF_EO2);
    float*         zs   = (float*)(sm + OFF_ZS);

    const int t  = threadIdx.x;
    const int bx = blockIdx.x;
    const int b  = bx >> 3;
    const int mt = bx & 7;
    const int m0 = mt * 128;

    const uint32_t smbase = (uint32_t)__cvta_generic_to_shared(sm);
    const char* hgbase = (const char*)(g_h + (size_t)b * NOPE * DOUT);

    const int m  = t & 127;
    const int oh = t >> 7;

    // packed adjacency: one word per chunk per thread (layout [b][ow][m])
    const uint32_t* adjw = g_adjp + (size_t)b * (NOPE / 32) * NMAC + m0 + m;

    // stage H chunk ch into buffer buf
    auto stageH = [&](int ch, int buf) {
        const char* hg = hgbase + (size_t)ch * CHUNK * DOUT * 2;
        uint32_t hD = smbase + OFF_H + (uint32_t)(buf * H_BYTES);
#pragma unroll
        for (int j = 0; j < 2; ++j) {
            int i = t + 256 * j, r = i >> 4, s = i & 15;
            cpa16(hD + (uint32_t)(r * H_PITCH * 2 + s * 16),
                  hg + (size_t)r * DOUT * 2 + s * 16);
        }
    };

    // prologue: H chunks 0,1 in flight; adj word 0 in register
    stageH(0, 0); cpa_commit();
    stageH(1, 1); cpa_commit();
    uint32_t wcur = __ldg(adjw);

    // per-o scalars for the full o-range (overlaps prologue loads)
    {
        const float* a0 = g_ao  + b * NOPE;
        const float* e1 = g_eo1 + b * NOPE;
        const float* e2 = g_eo2 + b * NOPE;
        for (int i = t; i < NOPE; i += 256) {
            aoS[i]  = a0[i];
            eo1S[i] = e1[i];
            eo2S[i] = e2[i];
        }
    }

    const float amv = g_am [b * NMAC + m0 + m];
    const float em1 = g_em1[b * NMAC + m0 + m];
    const float em2 = g_em2[b * NMAC + m0 + m];
    const float negam = -amv;

    const int warp = t >> 5, lane = t & 31;
    const int kw   = warp * 16;
    const int g    = lane >> 2, tig = lane & 3;

    const int a_or = (lane & 7) + ((lane & 16) >> 1);
    const uint32_t aAdr0 = smbase + OFF_H + (uint32_t)((a_or * H_PITCH + kw + (lane & 8)) * 2);
    const uint32_t aBdr  = smbase + OFF_W + (uint32_t)(lane * H_PITCH * 2);

    float acc[64];
#pragma unroll
    for (int i = 0; i < 64; ++i) acc[i] = 0.f;
    float zacc = 0.f;

    for (int ch = 0; ch < NCH; ++ch) {
        const int buf = ch % 3;
        asm volatile("cp.async.wait_group 1;\n" ::);   // H chunk ch landed
        __syncthreads();                                // visible; old buffer free

        if (ch + 2 < NCH) stageH(ch + 2, (ch + 2) % 3);
        cpa_commit();

        // prefetch next adjacency word (latency covered by W-gen + mma)
        uint32_t wnext = 0;
        if (ch + 1 < NCH) wnext = __ldg(adjw + (size_t)(ch + 1) * NMAC);

        // ---- W-gen from packed bits ----
        {
            const int ob = ch * CHUNK;
            const uint32_t bits = wcur;
#pragma unroll
            for (int j = 0; j < 16; ++j) {
                int ol = oh + 2 * j;
                float w = 0.f;
                if ((bits >> ol) & 1u) {
                    float ao = aoS[ob + ol];
                    w = (ao >= negam) ? eo1S[ob + ol] * em1 : eo2S[ob + ol] * em2;
                }
                Ws[ol * H_PITCH + m] = __float2bfloat16(w);
                zacc += w;
            }
        }
        __syncthreads();

        // ---- mma phase (32 o per chunk) ----
        const uint32_t aAdr = aAdr0 + (uint32_t)(buf * H_BYTES);
        uint32_t A0[4], A1[4];
        ldsm4t(A0[0], A0[1], A0[2], A0[3], aAdr);
        ldsm4t(A1[0], A1[1], A1[2], A1[3], aAdr + 16 * H_PITCH * 2);
#pragma unroll
        for (int nt = 0; nt < 16; ++nt) {
            uint32_t B0, B1, B2, B3;
            ldsm4t(B0, B1, B2, B3, aBdr + (uint32_t)(nt * 16));
            mma16816(acc + nt * 4, A0, B0, B1);
            mma16816(acc + nt * 4, A1, B2, B3);
        }
        wcur = wnext;
    }

    // ---- full Z reduction (complete in this CTA) ----
    __syncthreads();
    if (t < 128) zs[t] = zacc;
    __syncthreads();
    if (t >= 128) zs[t - 128] += zacc;
    __syncthreads();

    // ---- epilogue: out += numer / Z (out already holds exact h_res) ----
    float* ob = out + ((size_t)b * NMAC + m0) * DOUT;
#pragma unroll
    for (int nt = 0; nt < 16; ++nt) {
        int ma = nt * 8 + tig * 2;
        float iz0 = 1.0f / zs[ma];
        float iz1 = 1.0f / zs[ma + 1];
        int k = kw + g;
        float* p0 = ob + (size_t)ma * DOUT + k;
        float* p1 = ob + (size_t)(ma + 1) * DOUT + k;
        p0[0] += acc[nt * 4 + 0] * iz0;
        p1[0] += acc[nt * 4 + 1] * iz1;
        p0[8] += acc[nt * 4 + 2] * iz0;
        p1[8] += acc[nt * 4 + 3] * iz1;
    }
}

// ---------------- launch ----------------
extern "C" void kernel_launch(void* const* d_in, const int* in_sizes, int n_in,
                              void* d_out, int out_size)
{
    const int*   adj  = (const int*)d_in[0];
    const int*   bidx = (const int*)d_in[1];
    const float* fop  = (const float*)d_in[2];
    const float* fma  = (const float*)d_in[3];
    const float* ow   = (const float*)d_in[4];
    const float* mw   = (const float*)d_in[5];
    const float* oa   = (const float*)d_in[6];
    const float* ma   = (const float*)d_in[7];
    const float* rw   = (const float*)d_in[8];
    float* out = (float*)d_out;

    static bool attr_set = false;
    if (!attr_set) {
        cudaFuncSetAttribute(k3_attn, cudaFuncAttributeMaxDynamicSharedMemorySize, SMEM_K3);
        attr_set = true;
    }

    k_pre<<<PACK_BLOCKS + K1_BLOCKS + K2_BLOCKS, 256>>>(
        adj, bidx, fop, ow, oa, fma, rw, mw, ma, out);
    k3_attn<<<NB * 8, 256, SMEM_K3>>>(out);
}